// round 11
// baseline (speedup 1.0000x reference)
#include <cuda_runtime.h>
#include <cuda_bf16.h>

// Piecewise-linear LUT (65 knots, uniform grid [-8,8], h=0.25).
// Exact searchsorted(side='right') index with NO fixup:
//   idx = floor(4x + 32) = floor(4x) + 32, and 4*x is EXACT in fp32
//   (power-of-two multiply), so __float2int_rd(4x) + 32 is the exact index.
// Per element: FMUL + F2I + 2*IMNMX + conflict-free LDS.64 + FFMA.
// Out-of-range and the reference's "+1 for x >= xs[63]" quirk live in
// sentinel records 0 / 65 and record 64's intercept.
//
// R11: persistent grid-stride kernel (grid = 152 SMs x 8 CTAs). The
// replicated-LUT prologue is paid once per resident CTA (1216x) instead of
// once per tile (16384x), removing the wave-transition bubbles where fresh
// CTAs table-build instead of streaming. Hot path unchanged from the best
// measured config: TPB=256, VPT=4, __ldcs/__stcs, conflict-free LDS.64.

#define NPTS 65
#define NSEG 64
#define NREC 66   // record j covers segment j-1; j=0 below-range, j=65 above
#define VPT  4    // float4s per thread per tile
#define TPB  256
#define GRID_PERSIST (152 * 8)   // GB300: 152 SMs, 8 CTAs/SM at 32 regs/256 thr

__device__ __forceinline__ float eval_rec(float xv,
                                          const float2* __restrict__ p_lane)
{
    // i = floor(4x), exact (power-of-two multiply). Record = i+33 in [0,65].
    int i = __float2int_rd(xv * 4.0f);
    i = max(-33, min(i, 32));
    float2 ab = p_lane[i * 32];            // lane-private bank pair: conflict-free
    return fmaf(ab.x, xv, ab.y);
}

__device__ __forceinline__ void build_table(const float* __restrict__ table,
                                            float2* s_ab0, float2* s_ab, int t)
{
    if (t < NREC) {
        float a, b;
        if (t == 0)             { a = 0.0f; b = 0.0f; }   // x < xs[0]
        else if (t == NREC - 1) { a = 0.0f; b = 1.0f; }   // x >= xs[64]
        else {
            int k = t - 1;                                 // segment 0..63
            float x0 = table[2 * k + 0],     y0 = table[2 * k + 1];
            float x1 = table[2 * k + 2],     y1 = table[2 * k + 3];
            a = (y1 - y0) / (x1 - x0);
            b = y0 - a * x0;
            if (k == NSEG - 1) b += 1.0f;  // fold "+1 for x >= xs[63]"
        }
        s_ab0[t] = make_float2(a, b);
    }
    __syncthreads();
    for (int i = t; i < NREC * 32; i += blockDim.x)
        s_ab[i] = s_ab0[i >> 5];
    __syncthreads();
}

__device__ __forceinline__ float4 eval4(float4 v, const float2* p_lane)
{
    float4 r;
    r.x = eval_rec(v.x, p_lane);
    r.y = eval_rec(v.y, p_lane);
    r.z = eval_rec(v.z, p_lane);
    r.w = eval_rec(v.w, p_lane);
    return r;
}

// Persistent grid-stride kernel: each CTA loops over tiles of TPB*VPT float4s.
__global__ void __launch_bounds__(TPB, 8)
cSigmoid_pwl_kernel(const float4* __restrict__ x4,
                    const float*  __restrict__ table,
                    float4* __restrict__ out4,
                    int n4)
{
    __shared__ float2 s_ab0[NREC];
    __shared__ float2 s_ab[NREC * 32];

    int t = threadIdx.x;
    build_table(table, s_ab0, s_ab, t);

    // lane-private base, offset by +33 records so signed i indexes directly
    const float2* p_lane = s_ab + (t & 31) + 33 * 32;

    const int stride = gridDim.x * (TPB * VPT);
    int base = blockIdx.x * (TPB * VPT) + t;

    // Full tiles — no bounds checks in the hot loop.
    for (; base + (VPT - 1) * TPB < n4; base += stride) {
        float4 v[VPT];
#pragma unroll
        for (int k = 0; k < VPT; k++)
            v[k] = __ldcs(&x4[base + k * TPB]);
#pragma unroll
        for (int k = 0; k < VPT; k++)
            __stcs(&out4[base + k * TPB], eval4(v[k], p_lane));
    }

    // Partial tile (only the last tile can be partial).
#pragma unroll
    for (int k = 0; k < VPT; k++) {
        int i = base + k * TPB;
        if (i < n4) __stcs(&out4[i], eval4(__ldcs(&x4[i]), p_lane));
    }
}

// Scalar tail (n % 4 != 0); not hit for this shape but kept for generality.
__global__ void cSigmoid_pwl_tail_kernel(const float* __restrict__ x,
                                         const float* __restrict__ table,
                                         float* __restrict__ out,
                                         int start, int n)
{
    __shared__ float2 s_ab0[NREC];
    __shared__ float2 s_ab[NREC * 32];

    int t = threadIdx.x;
    build_table(table, s_ab0, s_ab, t);

    const float2* p_lane = s_ab + (t & 31) + 33 * 32;

    int i = start + blockIdx.x * blockDim.x + t;
    if (i < n) out[i] = eval_rec(x[i], p_lane);
}

extern "C" void kernel_launch(void* const* d_in, const int* in_sizes, int n_in,
                              void* d_out, int out_size)
{
    const float* x     = (const float*)d_in[0];
    const float* table = (const float*)d_in[1];
    float* out         = (float*)d_out;

    int n  = in_sizes[0];
    int n4 = n / 4;

    if (n4 > 0) {
        const int per_block = TPB * VPT;
        int tiles  = (n4 + per_block - 1) / per_block;
        int blocks = tiles < GRID_PERSIST ? tiles : GRID_PERSIST;
        cSigmoid_pwl_kernel<<<blocks, TPB>>>(
            (const float4*)x, table, (float4*)out, n4);
    }

    int tail = n - n4 * 4;
    if (tail > 0) {
        cSigmoid_pwl_tail_kernel<<<1, 256>>>(x, table, out, n4 * 4, n);
    }
}

// round 13
// speedup vs baseline: 1.1159x; 1.1159x over previous
#include <cuda_runtime.h>
#include <cuda_bf16.h>
#include <cstdint>

// Piecewise-linear LUT (65 knots, uniform grid [-8,8], h=0.25).
// Exact searchsorted(side='right') index with NO fixup:
//   idx = floor(4x + 32) = floor(4x) + 32, and 4*x is EXACT in fp32
//   (power-of-two multiply), so __float2int_rd(4x) + 32 is the exact index.
// Per element: FMUL + F2I + 2*IMNMX + conflict-free LDS.64 + FFMA.
// Out-of-range and the reference's "+1 for x >= xs[63]" quirk live in
// sentinel records 0 / 65 and record 64's intercept.
//
// R13 (= R12 with the compile fix): R10's best-measured tile structure
// (TPB=256, 16 floats/thread, front-batched, streaming hints) re-expressed
// with sm_100+ 256-bit global accesses (ld/st.global.cs.v8.f32): half the
// LDG/STG instructions and L1tex wavefronts per byte, 1024B contiguous per
// warp-instruction. float4 guarded fallback retained for general shapes.

#define NPTS 65
#define NSEG 64
#define NREC 66   // record j covers segment j-1; j=0 below-range, j=65 above
#define TPB  256

struct F8 { float v[8]; };

__device__ __forceinline__ F8 ldg256_cs(const float* __restrict__ p)
{
    F8 r;
    asm volatile("ld.global.cs.v8.f32 {%0,%1,%2,%3,%4,%5,%6,%7}, [%8];"
                 : "=f"(r.v[0]), "=f"(r.v[1]), "=f"(r.v[2]), "=f"(r.v[3]),
                   "=f"(r.v[4]), "=f"(r.v[5]), "=f"(r.v[6]), "=f"(r.v[7])
                 : "l"(p));
    return r;
}

__device__ __forceinline__ void stg256_cs(float* __restrict__ p, const F8& r)
{
    asm volatile("st.global.cs.v8.f32 [%0], {%1,%2,%3,%4,%5,%6,%7,%8};"
                 :: "l"(p),
                    "f"(r.v[0]), "f"(r.v[1]), "f"(r.v[2]), "f"(r.v[3]),
                    "f"(r.v[4]), "f"(r.v[5]), "f"(r.v[6]), "f"(r.v[7])
                 : "memory");
}

__device__ __forceinline__ float eval_rec(float xv,
                                          const float2* __restrict__ p_lane)
{
    // i = floor(4x), exact (power-of-two multiply). Record = i+33 in [0,65].
    int i = __float2int_rd(xv * 4.0f);
    i = max(-33, min(i, 32));
    float2 ab = p_lane[i * 32];            // lane-private bank pair: conflict-free
    return fmaf(ab.x, xv, ab.y);
}

__device__ __forceinline__ void build_table(const float* __restrict__ table,
                                            float2* s_ab0, float2* s_ab, int t)
{
    if (t < NREC) {
        float a, b;
        if (t == 0)             { a = 0.0f; b = 0.0f; }   // x < xs[0]
        else if (t == NREC - 1) { a = 0.0f; b = 1.0f; }   // x >= xs[64]
        else {
            int k = t - 1;                                 // segment 0..63
            float x0 = table[2 * k + 0],     y0 = table[2 * k + 1];
            float x1 = table[2 * k + 2],     y1 = table[2 * k + 3];
            a = (y1 - y0) / (x1 - x0);
            b = y0 - a * x0;
            if (k == NSEG - 1) b += 1.0f;  // fold "+1 for x >= xs[63]"
        }
        s_ab0[t] = make_float2(a, b);
    }
    __syncthreads();
    for (int i = t; i < NREC * 32; i += blockDim.x)
        s_ab[i] = s_ab0[i >> 5];
    __syncthreads();
}

__device__ __forceinline__ F8 eval8(F8 v, const float2* p_lane)
{
    F8 r;
#pragma unroll
    for (int k = 0; k < 8; k++) r.v[k] = eval_rec(v.v[k], p_lane);
    return r;
}

// Unguarded 256-bit kernel: host guarantees n == gridDim.x * TPB * 16.
// Each thread: 2 front-batched LDG.256 -> eval 16 elems -> 2 STG.256.
__global__ void __launch_bounds__(TPB, 8)
cSigmoid_pwl_kernel_v8(const float* __restrict__ x,
                       const float* __restrict__ table,
                       float* __restrict__ out)
{
    __shared__ float2 s_ab0[NREC];
    __shared__ float2 s_ab[NREC * 32];

    int t = threadIdx.x;
    build_table(table, s_ab0, s_ab, t);

    const float2* p_lane = s_ab + (t & 31) + 33 * 32;

    // float8-unit indices: block tile = 2*TPB float8s
    long long i0 = (long long)blockIdx.x * (2 * TPB) + t;
    long long i1 = i0 + TPB;

    F8 a = ldg256_cs(x + i0 * 8);
    F8 b = ldg256_cs(x + i1 * 8);
    stg256_cs(out + i0 * 8, eval8(a, p_lane));
    stg256_cs(out + i1 * 8, eval8(b, p_lane));
}

// Guarded float4 fallback (general n4).
__global__ void __launch_bounds__(TPB, 8)
cSigmoid_pwl_kernel(const float4* __restrict__ x4,
                    const float*  __restrict__ table,
                    float4* __restrict__ out4,
                    int n4)
{
    __shared__ float2 s_ab0[NREC];
    __shared__ float2 s_ab[NREC * 32];

    int t = threadIdx.x;
    build_table(table, s_ab0, s_ab, t);

    const float2* p_lane = s_ab + (t & 31) + 33 * 32;

    int base = blockIdx.x * (TPB * 4) + t;

#pragma unroll
    for (int k = 0; k < 4; k++) {
        int i = base + k * TPB;
        if (i < n4) {
            float4 v = __ldcs(&x4[i]);
            float4 r;
            r.x = eval_rec(v.x, p_lane);
            r.y = eval_rec(v.y, p_lane);
            r.z = eval_rec(v.z, p_lane);
            r.w = eval_rec(v.w, p_lane);
            __stcs(&out4[i], r);
        }
    }
}

// Scalar tail (n % 4 != 0); not hit for this shape but kept for generality.
__global__ void cSigmoid_pwl_tail_kernel(const float* __restrict__ x,
                                         const float* __restrict__ table,
                                         float* __restrict__ out,
                                         int start, int n)
{
    __shared__ float2 s_ab0[NREC];
    __shared__ float2 s_ab[NREC * 32];

    int t = threadIdx.x;
    build_table(table, s_ab0, s_ab, t);

    const float2* p_lane = s_ab + (t & 31) + 33 * 32;

    int i = start + blockIdx.x * blockDim.x + t;
    if (i < n) out[i] = eval_rec(x[i], p_lane);
}

extern "C" void kernel_launch(void* const* d_in, const int* in_sizes, int n_in,
                              void* d_out, int out_size)
{
    const float* x     = (const float*)d_in[0];
    const float* table = (const float*)d_in[1];
    float* out         = (float*)d_out;

    int n = in_sizes[0];

    // 256-bit path: n divisible by per-grid tile (16 floats/thread) and
    // 32B-aligned pointers (cudaMalloc guarantees 256B).
    const long long per_block_f = (long long)TPB * 16;
    bool aligned = ((((unsigned long long)(size_t)x) |
                     ((unsigned long long)(size_t)out)) & 31ULL) == 0ULL;

    if (aligned && n > 0 && ((long long)n % per_block_f) == 0) {
        int blocks = (int)((long long)n / per_block_f);
        cSigmoid_pwl_kernel_v8<<<blocks, TPB>>>(x, table, out);
        return;
    }

    int n4 = n / 4;
    if (n4 > 0) {
        int per_block = TPB * 4;
        int blocks = (n4 + per_block - 1) / per_block;
        cSigmoid_pwl_kernel<<<blocks, TPB>>>(
            (const float4*)x, table, (float4*)out, n4);
    }
    int tail = n - n4 * 4;
    if (tail > 0) {
        cSigmoid_pwl_tail_kernel<<<1, 256>>>(x, table, out, n4 * 4, n);
    }
}